// round 2
// baseline (speedup 1.0000x reference)
#include <cuda_runtime.h>
#include <cstdint>

#define BB 32
#define TT 2048
#define HH 1024
#define UU 1024

// Scratch (no allocations allowed)
__device__ float g_dec_proj[BB * UU];       // [B, U]
__device__ float g_score[BB * TT];          // [B, T] -> becomes alpha in-place
__device__ float g_ctx_part[4][BB * HH];    // T-split partials for context

__device__ __forceinline__ float tanh_fast(float x) {
    float y;
    asm("tanh.approx.f32 %0, %1;" : "=f"(y) : "f"(x));
    return y;
}

// ---------------------------------------------------------------------------
// K1: dec_proj[b,u] = sum_h dec_hidden[b,h] * Wa[h,u]
// grid: (B), block: 256 threads, each thread owns 4 u's (strided by 256)
// ---------------------------------------------------------------------------
__global__ __launch_bounds__(256) void k_dec_proj(const float* __restrict__ dec_hidden,
                                                  const float* __restrict__ Wa) {
    int b = blockIdx.x;
    int u0 = threadIdx.x;
    float acc0 = 0.f, acc1 = 0.f, acc2 = 0.f, acc3 = 0.f;
    const float* dh = dec_hidden + b * HH;
    for (int h = 0; h < HH; ++h) {
        float d = dh[h];
        const float* w = Wa + (size_t)h * UU;
        acc0 += d * w[u0];
        acc1 += d * w[u0 + 256];
        acc2 += d * w[u0 + 512];
        acc3 += d * w[u0 + 768];
    }
    g_dec_proj[b * UU + u0]       = acc0;
    g_dec_proj[b * UU + u0 + 256] = acc1;
    g_dec_proj[b * UU + u0 + 512] = acc2;
    g_dec_proj[b * UU + u0 + 768] = acc3;
}

// ---------------------------------------------------------------------------
// K2 (dominant): fused score kernel.
// score[b,t] = sum_u Va[u] * tanh( enc_out[b,t,:]·Ua[:,u] + dec_proj[b,u] )
// Tiled SGEMM: each block = 64 rows (one b, 64 consecutive t), loops over
// 16 u-tiles of 64, K=1024 in chunks of 16. 256 threads, 4x4 microtile.
// Epilogue (tanh + Va dot) fused per u-tile; score reduced across threads.
// ---------------------------------------------------------------------------
#define TM 64
#define TN 64
#define TK 16

__global__ __launch_bounds__(256) void k_score(const float* __restrict__ enc,
                                               const float* __restrict__ Ua,
                                               const float* __restrict__ Va) {
    __shared__ float As[TK][TM];       // transposed A tile
    __shared__ float Bs[TK][TN];
    __shared__ float s_dec[TN];
    __shared__ float s_va[TN];
    __shared__ float red[TM][16];

    const int blk = blockIdx.x;            // 1024 blocks
    const int r0  = blk * TM;              // global row (b*T + t)
    const int b   = r0 / TT;
    const int tid = threadIdx.x;
    const int tx  = tid & 15;              // u sub-index
    const int ty  = tid >> 4;              // row sub-index

    const int a_row = tid >> 2;            // A-load: row 0..63
    const int a_f4  = tid & 3;             // A-load: which float4 of 16 cols
    const int b_row = tid >> 4;            // B-load: k row 0..15
    const int b_c4  = tid & 15;            // B-load: which float4 of 64 cols

    float partial[4] = {0.f, 0.f, 0.f, 0.f};

    const float* encA = enc + (size_t)r0 * HH;

    for (int u0 = 0; u0 < UU; u0 += TN) {
        if (tid < TN) {
            s_dec[tid] = g_dec_proj[b * UU + u0 + tid];
            s_va[tid]  = Va[u0 + tid];
        }
        float acc[4][4] = {};

        for (int k0 = 0; k0 < HH; k0 += TK) {
            // Load A tile (64 x 16), store transposed into As[k][m]
            float4 a = *reinterpret_cast<const float4*>(
                encA + (size_t)a_row * HH + k0 + a_f4 * 4);
            As[a_f4 * 4 + 0][a_row] = a.x;
            As[a_f4 * 4 + 1][a_row] = a.y;
            As[a_f4 * 4 + 2][a_row] = a.z;
            As[a_f4 * 4 + 3][a_row] = a.w;
            // Load B tile (16 x 64)
            float4 bv = *reinterpret_cast<const float4*>(
                Ua + (size_t)(k0 + b_row) * UU + u0 + b_c4 * 4);
            *reinterpret_cast<float4*>(&Bs[b_row][b_c4 * 4]) = bv;
            __syncthreads();

            #pragma unroll
            for (int k = 0; k < TK; ++k) {
                float ra0 = As[k][ty * 4 + 0];
                float ra1 = As[k][ty * 4 + 1];
                float ra2 = As[k][ty * 4 + 2];
                float ra3 = As[k][ty * 4 + 3];
                float rb0 = Bs[k][tx * 4 + 0];
                float rb1 = Bs[k][tx * 4 + 1];
                float rb2 = Bs[k][tx * 4 + 2];
                float rb3 = Bs[k][tx * 4 + 3];
                acc[0][0] += ra0 * rb0; acc[0][1] += ra0 * rb1;
                acc[0][2] += ra0 * rb2; acc[0][3] += ra0 * rb3;
                acc[1][0] += ra1 * rb0; acc[1][1] += ra1 * rb1;
                acc[1][2] += ra1 * rb2; acc[1][3] += ra1 * rb3;
                acc[2][0] += ra2 * rb0; acc[2][1] += ra2 * rb1;
                acc[2][2] += ra2 * rb2; acc[2][3] += ra2 * rb3;
                acc[3][0] += ra3 * rb0; acc[3][1] += ra3 * rb1;
                acc[3][2] += ra3 * rb2; acc[3][3] += ra3 * rb3;
            }
            __syncthreads();
        }

        // Fused epilogue: tanh(acc + dec_proj) * Va, reduce along u into partial
        #pragma unroll
        for (int i = 0; i < 4; ++i) {
            #pragma unroll
            for (int j = 0; j < 4; ++j) {
                int u = tx * 4 + j;
                float s = tanh_fast(acc[i][j] + s_dec[u]);
                partial[i] += s * s_va[u];
            }
        }
        __syncthreads();   // protect s_dec/s_va before next tile overwrites
    }

    // Cross-thread reduction: sum partial over the 16 tx lanes per row
    #pragma unroll
    for (int i = 0; i < 4; ++i) red[ty * 4 + i][tx] = partial[i];
    __syncthreads();
    if (tid < TM) {
        float s = 0.f;
        #pragma unroll
        for (int j = 0; j < 16; ++j) s += red[tid][j];
        g_score[r0 + tid] = s;
    }
}

// ---------------------------------------------------------------------------
// K3: softmax over T, in place on g_score. grid: (B), 256 threads.
// ---------------------------------------------------------------------------
__global__ __launch_bounds__(256) void k_softmax() {
    int b = blockIdx.x;
    int tid = threadIdx.x;
    __shared__ float sm[256];
    float* sc = g_score + b * TT;

    float m = -1e30f;
    for (int t = tid; t < TT; t += 256) m = fmaxf(m, sc[t]);
    sm[tid] = m;
    __syncthreads();
    for (int s = 128; s > 0; s >>= 1) {
        if (tid < s) sm[tid] = fmaxf(sm[tid], sm[tid + s]);
        __syncthreads();
    }
    m = sm[0];
    __syncthreads();

    float sum = 0.f;
    for (int t = tid; t < TT; t += 256) {
        float e = __expf(sc[t] - m);
        sc[t] = e;
        sum += e;
    }
    sm[tid] = sum;
    __syncthreads();
    for (int s = 128; s > 0; s >>= 1) {
        if (tid < s) sm[tid] += sm[tid + s];
        __syncthreads();
    }
    float inv = 1.f / sm[0];
    for (int t = tid; t < TT; t += 256) sc[t] *= inv;
}

// ---------------------------------------------------------------------------
// K4: context partials. grid: (B, H/256, 4), block 256.
// Each block sums 512 t's for 256 h's.
// ---------------------------------------------------------------------------
__global__ __launch_bounds__(256) void k_ctx_part(const float* __restrict__ enc) {
    int b  = blockIdx.x;
    int hc = blockIdx.y;
    int tc = blockIdx.z;
    int h  = hc * 256 + threadIdx.x;
    int t0 = tc * 512;

    __shared__ float s_al[512];
    for (int i = threadIdx.x; i < 512; i += 256) s_al[i] = g_score[b * TT + t0 + i];
    __syncthreads();

    float acc = 0.f;
    const float* e = enc + ((size_t)b * TT + t0) * HH + h;
    #pragma unroll 8
    for (int t = 0; t < 512; ++t) acc += s_al[t] * e[(size_t)t * HH];
    g_ctx_part[tc][b * HH + h] = acc;
}

// K5: final reduce of 4 T-partials -> out[B*H]
__global__ __launch_bounds__(256) void k_ctx_final(float* __restrict__ out) {
    int idx = blockIdx.x * 256 + threadIdx.x;   // B*H = 32768
    out[idx] = g_ctx_part[0][idx] + g_ctx_part[1][idx]
             + g_ctx_part[2][idx] + g_ctx_part[3][idx];
}

// ---------------------------------------------------------------------------
extern "C" void kernel_launch(void* const* d_in, const int* in_sizes, int n_in,
                              void* d_out, int out_size) {
    const float* enc = (const float*)d_in[0];   // [B, T, H]
    const float* dec = (const float*)d_in[1];   // [B, H]
    const float* Wa  = (const float*)d_in[2];   // [H, U]
    const float* Ua  = (const float*)d_in[3];   // [H, U]
    const float* Va  = (const float*)d_in[4];   // [U]
    float* out = (float*)d_out;                 // [B, H]

    k_dec_proj<<<BB, 256>>>(dec, Wa);
    k_score<<<(BB * TT) / TM, 256>>>(enc, Ua, Va);
    k_softmax<<<BB, 256>>>();
    dim3 gctx(BB, HH / 256, 4);
    k_ctx_part<<<gctx, 256>>>(enc);
    k_ctx_final<<<(BB * HH) / 256, 256>>>(out);
}

// round 4
// speedup vs baseline: 1.5999x; 1.5999x over previous
#include <cuda_runtime.h>
#include <cstdint>

#define BB 32
#define TT 2048
#define HH 1024
#define UU 1024

// Scratch (no allocations allowed)
__device__ float g_dec_proj[BB * UU];       // [B, U]
__device__ float g_score[BB * TT];          // [B, T] -> becomes alpha in-place
__device__ float g_ctx_part[4][BB * HH];    // T-split partials for context

__device__ __forceinline__ float tanh_fast(float x) {
    float y;
    asm("tanh.approx.f32 %0, %1;" : "=f"(y) : "f"(x));
    return y;
}

// ---------------------------------------------------------------------------
// K1: dec_proj[b,u] = sum_h dec_hidden[b,h] * Wa[h,u]
// grid: (B), block: 256 threads, each thread owns 4 u's (strided by 256)
// ---------------------------------------------------------------------------
__global__ __launch_bounds__(256) void k_dec_proj(const float* __restrict__ dec_hidden,
                                                  const float* __restrict__ Wa) {
    int b = blockIdx.x;
    int u0 = threadIdx.x;
    float acc0 = 0.f, acc1 = 0.f, acc2 = 0.f, acc3 = 0.f;
    const float* dh = dec_hidden + b * HH;
    for (int h = 0; h < HH; ++h) {
        float d = dh[h];
        const float* w = Wa + (size_t)h * UU;
        acc0 += d * w[u0];
        acc1 += d * w[u0 + 256];
        acc2 += d * w[u0 + 512];
        acc3 += d * w[u0 + 768];
    }
    g_dec_proj[b * UU + u0]       = acc0;
    g_dec_proj[b * UU + u0 + 256] = acc1;
    g_dec_proj[b * UU + u0 + 512] = acc2;
    g_dec_proj[b * UU + u0 + 768] = acc3;
}

// ---------------------------------------------------------------------------
// K2 (dominant): fused score kernel.
// score[b,t] = sum_u Va[u] * tanh( enc_out[b,t,:]·Ua[:,u] + dec_proj[b,u] )
// Tiled SGEMM: each block = 64 rows (one b, 64 consecutive t), loops over
// 16 u-tiles of 64, K=1024 in chunks of 16. 256 threads, 4x4 microtile.
// Epilogue (tanh + Va dot) fused per u-tile; score reduced across threads.
// ---------------------------------------------------------------------------
#define TM 64
#define TN 64
#define TK 16

__global__ __launch_bounds__(256) void k_score(const float* __restrict__ enc,
                                               const float* __restrict__ Ua,
                                               const float* __restrict__ Va) {
    __shared__ float As[TK][TM];       // transposed A tile
    __shared__ float Bs[TK][TN];
    __shared__ float s_dec[TN];
    __shared__ float s_va[TN];
    __shared__ float red[TM][16];

    const int blk = blockIdx.x;            // 1024 blocks
    const int r0  = blk * TM;              // global row (b*T + t)
    const int b   = r0 / TT;
    const int tid = threadIdx.x;
    const int tx  = tid & 15;              // u sub-index
    const int ty  = tid >> 4;              // row sub-index

    const int a_row = tid >> 2;            // A-load: row 0..63
    const int a_f4  = tid & 3;             // A-load: which float4 of 16 cols
    const int b_row = tid >> 4;            // B-load: k row 0..15
    const int b_c4  = tid & 15;            // B-load: which float4 of 64 cols

    float partial[4] = {0.f, 0.f, 0.f, 0.f};

    const float* encA = enc + (size_t)r0 * HH;

    for (int u0 = 0; u0 < UU; u0 += TN) {
        if (tid < TN) {
            s_dec[tid] = g_dec_proj[b * UU + u0 + tid];
            s_va[tid]  = Va[u0 + tid];
        }
        float acc[4][4] = {};

        for (int k0 = 0; k0 < HH; k0 += TK) {
            // Load A tile (64 x 16), store transposed into As[k][m]
            float4 a = *reinterpret_cast<const float4*>(
                encA + (size_t)a_row * HH + k0 + a_f4 * 4);
            As[a_f4 * 4 + 0][a_row] = a.x;
            As[a_f4 * 4 + 1][a_row] = a.y;
            As[a_f4 * 4 + 2][a_row] = a.z;
            As[a_f4 * 4 + 3][a_row] = a.w;
            // Load B tile (16 x 64)
            float4 bv = *reinterpret_cast<const float4*>(
                Ua + (size_t)(k0 + b_row) * UU + u0 + b_c4 * 4);
            *reinterpret_cast<float4*>(&Bs[b_row][b_c4 * 4]) = bv;
            __syncthreads();

            #pragma unroll
            for (int k = 0; k < TK; ++k) {
                float ra0 = As[k][ty * 4 + 0];
                float ra1 = As[k][ty * 4 + 1];
                float ra2 = As[k][ty * 4 + 2];
                float ra3 = As[k][ty * 4 + 3];
                float rb0 = Bs[k][tx * 4 + 0];
                float rb1 = Bs[k][tx * 4 + 1];
                float rb2 = Bs[k][tx * 4 + 2];
                float rb3 = Bs[k][tx * 4 + 3];
                acc[0][0] += ra0 * rb0; acc[0][1] += ra0 * rb1;
                acc[0][2] += ra0 * rb2; acc[0][3] += ra0 * rb3;
                acc[1][0] += ra1 * rb0; acc[1][1] += ra1 * rb1;
                acc[1][2] += ra1 * rb2; acc[1][3] += ra1 * rb3;
                acc[2][0] += ra2 * rb0; acc[2][1] += ra2 * rb1;
                acc[2][2] += ra2 * rb2; acc[2][3] += ra2 * rb3;
                acc[3][0] += ra3 * rb0; acc[3][1] += ra3 * rb1;
                acc[3][2] += ra3 * rb2; acc[3][3] += ra3 * rb3;
            }
            __syncthreads();
        }

        // Fused epilogue: tanh(acc + dec_proj) * Va, reduce along u into partial
        #pragma unroll
        for (int i = 0; i < 4; ++i) {
            #pragma unroll
            for (int j = 0; j < 4; ++j) {
                int u = tx * 4 + j;
                float s = tanh_fast(acc[i][j] + s_dec[u]);
                partial[i] += s * s_va[u];
            }
        }
        __syncthreads();   // protect s_dec/s_va before next tile overwrites
    }

    // Cross-thread reduction: sum partial over the 16 tx lanes per row
    #pragma unroll
    for (int i = 0; i < 4; ++i) red[ty * 4 + i][tx] = partial[i];
    __syncthreads();
    if (tid < TM) {
        float s = 0.f;
        #pragma unroll
        for (int j = 0; j < 16; ++j) s += red[tid][j];
        g_score[r0 + tid] = s;
    }
}

// ---------------------------------------------------------------------------
// K3: softmax over T, in place on g_score. grid: (B), 256 threads.
// ---------------------------------------------------------------------------
__global__ __launch_bounds__(256) void k_softmax() {
    int b = blockIdx.x;
    int tid = threadIdx.x;
    __shared__ float sm[256];
    float* sc = g_score + b * TT;

    float m = -1e30f;
    for (int t = tid; t < TT; t += 256) m = fmaxf(m, sc[t]);
    sm[tid] = m;
    __syncthreads();
    for (int s = 128; s > 0; s >>= 1) {
        if (tid < s) sm[tid] = fmaxf(sm[tid], sm[tid + s]);
        __syncthreads();
    }
    m = sm[0];
    __syncthreads();

    float sum = 0.f;
    for (int t = tid; t < TT; t += 256) {
        float e = __expf(sc[t] - m);
        sc[t] = e;
        sum += e;
    }
    sm[tid] = sum;
    __syncthreads();
    for (int s = 128; s > 0; s >>= 1) {
        if (tid < s) sm[tid] += sm[tid + s];
        __syncthreads();
    }
    float inv = 1.f / sm[0];
    for (int t = tid; t < TT; t += 256) sc[t] *= inv;
}

// ---------------------------------------------------------------------------
// K4: context partials. grid: (B, H/256, 4), block 256.
// Each block sums 512 t's for 256 h's.
// ---------------------------------------------------------------------------
__global__ __launch_bounds__(256) void k_ctx_part(const float* __restrict__ enc) {
    int b  = blockIdx.x;
    int hc = blockIdx.y;
    int tc = blockIdx.z;
    int h  = hc * 256 + threadIdx.x;
    int t0 = tc * 512;

    __shared__ float s_al[512];
    for (int i = threadIdx.x; i < 512; i += 256) s_al[i] = g_score[b * TT + t0 + i];
    __syncthreads();

    float acc = 0.f;
    const float* e = enc + ((size_t)b * TT + t0) * HH + h;
    #pragma unroll 8
    for (int t = 0; t < 512; ++t) acc += s_al[t] * e[(size_t)t * HH];
    g_ctx_part[tc][b * HH + h] = acc;
}

// K5: final reduce of 4 T-partials -> out[B*H]
__global__ __launch_bounds__(256) void k_ctx_final(float* __restrict__ out) {
    int idx = blockIdx.x * 256 + threadIdx.x;   // B*H = 32768
    out[idx] = g_ctx_part[0][idx] + g_ctx_part[1][idx]
             + g_ctx_part[2][idx] + g_ctx_part[3][idx];
}

// ---------------------------------------------------------------------------
extern "C" void kernel_launch(void* const* d_in, const int* in_sizes, int n_in,
                              void* d_out, int out_size) {
    const float* enc = (const float*)d_in[0];   // [B, T, H]
    const float* dec = (const float*)d_in[1];   // [B, H]
    const float* Wa  = (const float*)d_in[2];   // [H, U]
    const float* Ua  = (const float*)d_in[3];   // [H, U]
    const float* Va  = (const float*)d_in[4];   // [U]
    float* out = (float*)d_out;                 // [B, H]

    k_dec_proj<<<BB, 256>>>(dec, Wa);
    k_score<<<(BB * TT) / TM, 256>>>(enc, Ua, Va);
    k_softmax<<<BB, 256>>>();
    dim3 gctx(BB, HH / 256, 4);
    k_ctx_part<<<gctx, 256>>>(enc);
    k_ctx_final<<<(BB * HH) / 256, 256>>>(out);
}

// round 6
// speedup vs baseline: 7.1105x; 4.4444x over previous
#include <cuda_runtime.h>
#include <cstdint>

#define BB 32
#define TT 2048
#define HH 1024
#define UU 1024
#define BT (BB*TT)

// score GEMM tiling
#define TM 128
#define TN 128
#define KC 32
#define NCHUNK (HH/KC)    // 32
#define NBLK (UU/TN)      // 8

// SMEM pitches (floats) — padded for conflict-free fragment LDS
#define APITCH 36         // 32 + 4 pad  -> bank = (4g+tc)%32, all distinct
#define BPITCH 136        // 128 + 8 pad -> bank = (8tc+g)%32, all distinct
#define ABYTES (TM*APITCH*4)       // 18432
#define BBYTES (KC*BPITCH*4)       // 17408
#define BUFBYTES (ABYTES+BBYTES)   // 35840
#define SM_DEC (2*BUFBYTES)        // 71680
#define SM_VA  (SM_DEC + TN*4)
#define SM_RED (SM_VA + TN*4)
#define SMEM_TOTAL (SM_RED + TM*4*4)   // 74752

// Scratch
__device__ float g_dec_proj[BB*UU];
__device__ float g_score_part[NBLK][BT];
__device__ float g_score[BT];
__device__ float g_ctx_part[8][BB*HH];

__device__ __forceinline__ float tanh_fast(float x) {
    float y; asm("tanh.approx.f32 %0, %1;" : "=f"(y) : "f"(x)); return y;
}
__device__ __forceinline__ uint32_t smem_u32(const void* p) {
    uint32_t a;
    asm("{ .reg .u64 t; cvta.to.shared.u64 t, %1; cvt.u32.u64 %0, t; }" : "=r"(a) : "l"(p));
    return a;
}
__device__ __forceinline__ void cpasync16(uint32_t dst, const void* src) {
    asm volatile("cp.async.cg.shared.global [%0], [%1], 16;" :: "r"(dst), "l"(src));
}
__device__ __forceinline__ uint32_t f2tf(float x) {
    uint32_t r; asm("cvt.rna.tf32.f32 %0, %1;" : "=r"(r) : "f"(x)); return r;
}
__device__ __forceinline__ void sts128u(uint32_t addr, uint32_t a, uint32_t b,
                                        uint32_t c, uint32_t d) {
    asm volatile("st.shared.v4.b32 [%0], {%1,%2,%3,%4};"
                 :: "r"(addr), "r"(a), "r"(b), "r"(c), "r"(d) : "memory");
}
__device__ __forceinline__ void mma_tf32(float* d, const uint32_t* a,
                                         uint32_t b0, uint32_t b1) {
    asm volatile(
        "mma.sync.aligned.m16n8k8.row.col.f32.tf32.tf32.f32 "
        "{%0,%1,%2,%3}, {%4,%5,%6,%7}, {%8,%9}, {%0,%1,%2,%3};"
        : "+f"(d[0]), "+f"(d[1]), "+f"(d[2]), "+f"(d[3])
        : "r"(a[0]), "r"(a[1]), "r"(a[2]), "r"(a[3]), "r"(b0), "r"(b1));
}

// ---------------------------------------------------------------------------
// dec_proj[b,u] = dec_hidden[b,:] @ Wa.  grid (B, 4), 256 thr.
// ---------------------------------------------------------------------------
__global__ __launch_bounds__(256) void k_dec_proj(const float* __restrict__ dec,
                                                  const float* __restrict__ Wa) {
    __shared__ float dh[HH];
    int b = blockIdx.x;
    int u = blockIdx.y * 256 + threadIdx.x;
    for (int i = threadIdx.x; i < HH; i += 256) dh[i] = dec[b * HH + i];
    __syncthreads();
    float acc = 0.f;
    #pragma unroll 8
    for (int h = 0; h < HH; ++h) acc += dh[h] * Wa[(size_t)h * UU + u];
    g_dec_proj[b * UU + u] = acc;
}

// ---------------------------------------------------------------------------
// Dominant kernel: tf32 mma.sync GEMM (enc @ Ua) with fused tanh/Va epilogue.
// grid = (NBLK=8, BT/TM=512), block = 256 (8 warps of 64x32 tiles).
// ---------------------------------------------------------------------------
__global__ void __launch_bounds__(256, 2)
k_score_mma(const float* __restrict__ enc,
            const float* __restrict__ Ua,
            const float* __restrict__ Va) {
    extern __shared__ __align__(16) char smem[];
    const uint32_t sb = smem_u32(smem);
    const int tid  = threadIdx.x;
    const int lane = tid & 31;
    const int wid  = tid >> 5;
    const int g    = lane >> 2;       // groupID
    const int tc   = lane & 3;        // threadID_in_group
    const int Mw   = wid & 1;         // warp M row (0/1)
    const int Nw   = wid >> 1;        // warp N col (0..3)

    const int u0 = blockIdx.x * TN;
    const int r0 = blockIdx.y * TM;
    const int b  = blockIdx.y >> 4;   // r0 / TT

    float* s_dec = (float*)(smem + SM_DEC);
    float* s_va  = (float*)(smem + SM_VA);
    float* s_red = (float*)(smem + SM_RED);
    if (tid < TN) {
        s_dec[tid] = g_dec_proj[b * UU + u0 + tid];
        s_va[tid]  = Va[u0 + tid];
    }

    const float* Ag = enc + (size_t)r0 * HH;
    const float* Bg = Ua + u0;

    float d[4][4][4] = {};   // [Mtile][Ntile][reg]

    // ---- prologue: stage chunk 0 ----
    {
        const uint32_t ab = sb;           // buf0 A
        #pragma unroll
        for (int j = 0; j < 4; ++j) {
            int idx = tid + 256 * j;
            int row = idx >> 3, k4 = idx & 7;
            cpasync16(ab + row * (APITCH*4) + k4 * 16,
                      Ag + (size_t)row * HH + k4 * 4);
        }
        asm volatile("cp.async.commit_group;" ::: "memory");
        const uint32_t bb = sb + ABYTES;  // buf0 B
        #pragma unroll
        for (int j = 0; j < 4; ++j) {
            int idx = tid + 256 * j;
            int k = idx >> 5, n4 = idx & 31;
            float4 v = *(const float4*)(Bg + (size_t)k * UU + n4 * 4);
            sts128u(bb + k * (BPITCH*4) + n4 * 16,
                    f2tf(v.x), f2tf(v.y), f2tf(v.z), f2tf(v.w));
        }
    }

    // per-lane fragment base offsets (bytes, within a buffer)
    const uint32_t aLane = (uint32_t)((Mw * 64 + g) * (APITCH*4) + tc * 4);
    const uint32_t bLane = (uint32_t)(tc * (BPITCH*4) + (Nw * 32 + g) * 4);

    for (int c = 0; c < NCHUNK; ++c) {
        const int buf = c & 1;
        const uint32_t bufo = sb + (buf ? BUFBYTES : 0);
        const uint32_t nbufo = sb + (buf ? 0 : BUFBYTES);

        if (c + 1 < NCHUNK) {
            const int k0 = (c + 1) * KC;
            #pragma unroll
            for (int j = 0; j < 4; ++j) {
                int idx = tid + 256 * j;
                int row = idx >> 3, k4 = idx & 7;
                cpasync16(nbufo + row * (APITCH*4) + k4 * 16,
                          Ag + (size_t)row * HH + k0 + k4 * 4);
            }
            asm volatile("cp.async.commit_group;" ::: "memory");
            const uint32_t bb = nbufo + ABYTES;
            #pragma unroll
            for (int j = 0; j < 4; ++j) {
                int idx = tid + 256 * j;
                int k = idx >> 5, n4 = idx & 31;
                float4 v = *(const float4*)(Bg + (size_t)(k0 + k) * UU + n4 * 4);
                sts128u(bb + k * (BPITCH*4) + n4 * 16,
                        f2tf(v.x), f2tf(v.y), f2tf(v.z), f2tf(v.w));
            }
            asm volatile("cp.async.wait_group 1;" ::: "memory");
        } else {
            asm volatile("cp.async.wait_group 0;" ::: "memory");
        }
        __syncthreads();

        // ---- compute chunk c ----
        const uint32_t aB = bufo + aLane;
        const uint32_t bB = bufo + ABYTES + bLane;
        #pragma unroll
        for (int s = 0; s < 4; ++s) {
            uint32_t a[4][4];
            #pragma unroll
            for (int i = 0; i < 4; ++i) {
                const uint32_t* p = (const uint32_t*)(smem +
                    (aB - sb) + i * 16 * (APITCH*4) + s * 32);
                a[i][0] = p[0];
                a[i][1] = p[8 * APITCH];
                a[i][2] = p[4];
                a[i][3] = p[8 * APITCH + 4];
            }
            #pragma unroll
            for (int jn = 0; jn < 4; ++jn) {
                const uint32_t* q = (const uint32_t*)(smem +
                    (bB - sb) + s * 8 * (BPITCH*4) + jn * 32);
                uint32_t b0 = q[0];
                uint32_t b1 = q[4 * BPITCH];
                #pragma unroll
                for (int i = 0; i < 4; ++i)
                    mma_tf32(d[i][jn], a[i], b0, b1);
            }
        }
        __syncthreads();
    }

    // ---- fused epilogue: tanh(d + dec)*Va, reduce over u ----
    float rowacc[4][2] = {};
    #pragma unroll
    for (int i = 0; i < 4; ++i)
        #pragma unroll
        for (int jn = 0; jn < 4; ++jn)
            #pragma unroll
            for (int r = 0; r < 4; ++r) {
                int ul = Nw * 32 + jn * 8 + tc * 2 + (r & 1);
                float v = tanh_fast(d[i][jn][r] + s_dec[ul]) * s_va[ul];
                rowacc[i][r >> 1] += v;
            }
    // reduce over the 4 tc lanes of each quad
    #pragma unroll
    for (int i = 0; i < 4; ++i)
        #pragma unroll
        for (int h = 0; h < 2; ++h) {
            float v = rowacc[i][h];
            v += __shfl_xor_sync(0xffffffffu, v, 1);
            v += __shfl_xor_sync(0xffffffffu, v, 2);
            rowacc[i][h] = v;
        }
    if (tc == 0) {
        #pragma unroll
        for (int i = 0; i < 4; ++i)
            #pragma unroll
            for (int h = 0; h < 2; ++h) {
                int m = Mw * 64 + i * 16 + h * 8 + g;
                s_red[m * 4 + Nw] = rowacc[i][h];
            }
    }
    __syncthreads();
    if (tid < TM) {
        float s = s_red[tid * 4] + s_red[tid * 4 + 1]
                + s_red[tid * 4 + 2] + s_red[tid * 4 + 3];
        g_score_part[blockIdx.x][r0 + tid] = s;
    }
}

// ---------------------------------------------------------------------------
// Softmax over T (sums the 8 N-block partials). grid (B), 256 thr.
// ---------------------------------------------------------------------------
__global__ __launch_bounds__(256) void k_softmax() {
    int b = blockIdx.x, tid = threadIdx.x;
    __shared__ float sm[256];
    float* sc = g_score + b * TT;

    float m = -1e30f;
    for (int t = tid; t < TT; t += 256) {
        float v = 0.f;
        #pragma unroll
        for (int p = 0; p < NBLK; ++p) v += g_score_part[p][b * TT + t];
        sc[t] = v;
        m = fmaxf(m, v);
    }
    sm[tid] = m; __syncthreads();
    for (int s = 128; s > 0; s >>= 1) {
        if (tid < s) sm[tid] = fmaxf(sm[tid], sm[tid + s]);
        __syncthreads();
    }
    m = sm[0]; __syncthreads();

    float sum = 0.f;
    for (int t = tid; t < TT; t += 256) {
        float e = __expf(sc[t] - m);
        sc[t] = e; sum += e;
    }
    sm[tid] = sum; __syncthreads();
    for (int s = 128; s > 0; s >>= 1) {
        if (tid < s) sm[tid] += sm[tid + s];
        __syncthreads();
    }
    float inv = 1.f / sm[0];
    for (int t = tid; t < TT; t += 256) sc[t] *= inv;
}

// ---------------------------------------------------------------------------
// Context: grid (B, H/256, 8), block 256.
// ---------------------------------------------------------------------------
__global__ __launch_bounds__(256) void k_ctx_part(const float* __restrict__ enc) {
    int b = blockIdx.x, hc = blockIdx.y, tc = blockIdx.z;
    int h = hc * 256 + threadIdx.x;
    int t0 = tc * 256;
    __shared__ float s_al[256];
    s_al[threadIdx.x] = g_score[b * TT + t0 + threadIdx.x];
    __syncthreads();
    float acc = 0.f;
    const float* e = enc + ((size_t)b * TT + t0) * HH + h;
    #pragma unroll 16
    for (int t = 0; t < 256; ++t) acc += s_al[t] * e[(size_t)t * HH];
    g_ctx_part[tc][b * HH + h] = acc;
}

__global__ __launch_bounds__(256) void k_ctx_final(float* __restrict__ out) {
    int idx = blockIdx.x * 256 + threadIdx.x;
    float s = 0.f;
    #pragma unroll
    for (int p = 0; p < 8; ++p) s += g_ctx_part[p][idx];
    out[idx] = s;
}

// ---------------------------------------------------------------------------
extern "C" void kernel_launch(void* const* d_in, const int* in_sizes, int n_in,
                              void* d_out, int out_size) {
    const float* enc = (const float*)d_in[0];
    const float* dec = (const float*)d_in[1];
    const float* Wa  = (const float*)d_in[2];
    const float* Ua  = (const float*)d_in[3];
    const float* Va  = (const float*)d_in[4];
    float* out = (float*)d_out;

    static int smem_set = 0;
    if (!smem_set) {
        cudaFuncSetAttribute(k_score_mma,
                             cudaFuncAttributeMaxDynamicSharedMemorySize,
                             SMEM_TOTAL);
        smem_set = 1;
    }

    k_dec_proj<<<dim3(BB, 4), 256>>>(dec, Wa);
    k_score_mma<<<dim3(NBLK, BT / TM), 256, SMEM_TOTAL>>>(enc, Ua, Va);
    k_softmax<<<BB, 256>>>();
    k_ctx_part<<<dim3(BB, HH / 256, 8), 256>>>(enc);
    k_ctx_final<<<(BB * HH) / 256, 256>>>(out);
}

// round 9
// speedup vs baseline: 7.6389x; 1.0743x over previous
#include <cuda_runtime.h>
#include <cstdint>

#define BB 32
#define TT 2048
#define HH 1024
#define UU 1024
#define BT (BB*TT)

// score GEMM tiling
#define TM 128
#define TN 128
#define KC 32
#define NCHUNK (HH/KC)    // 32
#define NBLK (UU/TN)      // 8
#define STAGES 3

// SMEM pitches (floats) — padded for conflict-free fragment LDS
#define APITCH 36         // 32 + 4 pad
#define BPITCH 136        // 128 + 8 pad
#define ABYTES (TM*APITCH*4)       // 18432
#define BBYTES (KC*BPITCH*4)       // 17408
#define BUFBYTES (ABYTES+BBYTES)   // 35840
#define SM_DEC (STAGES*BUFBYTES)   // 107520
#define SM_VA  (SM_DEC + TN*4)
#define SM_RED (SM_VA + TN*4)
#define SMEM_TOTAL (SM_RED + TM*4*4)   // 110592

// Scratch
__device__ float g_dec_proj[BB*UU];
__device__ float g_score_part[NBLK][BT];
__device__ float g_score[BT];
__device__ float g_ctx_part[16][BB*HH];

__device__ __forceinline__ float tanh_fast(float x) {
    float y; asm("tanh.approx.f32 %0, %1;" : "=f"(y) : "f"(x)); return y;
}
__device__ __forceinline__ uint32_t smem_u32(const void* p) {
    uint32_t a;
    asm("{ .reg .u64 t; cvta.to.shared.u64 t, %1; cvt.u32.u64 %0, t; }" : "=r"(a) : "l"(p));
    return a;
}
__device__ __forceinline__ void cpasync16(uint32_t dst, const void* src) {
    asm volatile("cp.async.cg.shared.global [%0], [%1], 16;" :: "r"(dst), "l"(src));
}
__device__ __forceinline__ void mma_tf32(float* d, const uint32_t* a,
                                         uint32_t b0, uint32_t b1) {
    asm volatile(
        "mma.sync.aligned.m16n8k8.row.col.f32.tf32.tf32.f32 "
        "{%0,%1,%2,%3}, {%4,%5,%6,%7}, {%8,%9}, {%0,%1,%2,%3};"
        : "+f"(d[0]), "+f"(d[1]), "+f"(d[2]), "+f"(d[3])
        : "r"(a[0]), "r"(a[1]), "r"(a[2]), "r"(a[3]), "r"(b0), "r"(b1));
}

// ---------------------------------------------------------------------------
// dec_proj[b,u] = dec_hidden[b,:] @ Wa.  grid (B, 4), 256 thr.
// ---------------------------------------------------------------------------
__global__ __launch_bounds__(256) void k_dec_proj(const float* __restrict__ dec,
                                                  const float* __restrict__ Wa) {
    __shared__ float dh[HH];
    int b = blockIdx.x;
    int u = blockIdx.y * 256 + threadIdx.x;
    for (int i = threadIdx.x; i < HH; i += 256) dh[i] = dec[b * HH + i];
    __syncthreads();
    float acc = 0.f;
    #pragma unroll 8
    for (int h = 0; h < HH; ++h) acc += dh[h] * Wa[(size_t)h * UU + u];
    g_dec_proj[b * UU + u] = acc;
}

// ---------------------------------------------------------------------------
// Dominant kernel: tf32 mma.sync GEMM (enc @ Ua) with fused tanh/Va epilogue.
// 3-stage cp.async pipeline, one __syncthreads per K-chunk.
// grid = (NBLK=8, BT/TM=512), block = 256 (8 warps of 64x32 tiles).
// ---------------------------------------------------------------------------
__global__ void __launch_bounds__(256, 2)
k_score_mma(const float* __restrict__ enc,
            const float* __restrict__ Ua,
            const float* __restrict__ Va) {
    extern __shared__ __align__(16) char smem[];
    const uint32_t sb = smem_u32(smem);
    const int tid  = threadIdx.x;
    const int lane = tid & 31;
    const int wid  = tid >> 5;
    const int g    = lane >> 2;       // groupID
    const int tc   = lane & 3;        // threadID_in_group
    const int Mw   = wid & 1;         // warp M row (0/1)
    const int Nw   = wid >> 1;        // warp N col (0..3)

    const int u0 = blockIdx.x * TN;
    const int r0 = blockIdx.y * TM;
    const int b  = blockIdx.y >> 4;   // r0 / TT

    float* s_dec = (float*)(smem + SM_DEC);
    float* s_va  = (float*)(smem + SM_VA);
    float* s_red = (float*)(smem + SM_RED);
    if (tid < TN) {
        s_dec[tid] = g_dec_proj[b * UU + u0 + tid];
        s_va[tid]  = Va[u0 + tid];
    }

    const float* Ag = enc + (size_t)r0 * HH;
    const float* Bg = Ua + u0;

    // load indexing (per thread)
    const int a_row = tid >> 3, a_k4 = tid & 7;     // A: 4 rows apart of 32
    const int b_k   = tid >> 5, b_n4 = tid & 31;    // B: 8 k-rows apart of 32

    float d[4][4][4] = {};   // [Mtile][Ntile][reg]

    // ---- prologue: stage chunks 0 and 1 ----
    #pragma unroll
    for (int st = 0; st < STAGES - 1; ++st) {
        const uint32_t ab = sb + st * BUFBYTES;
        const int k0 = st * KC;
        #pragma unroll
        for (int j = 0; j < 4; ++j) {
            int row = a_row + 32 * j;
            cpasync16(ab + row * (APITCH*4) + a_k4 * 16,
                      Ag + (size_t)row * HH + k0 + a_k4 * 4);
        }
        #pragma unroll
        for (int j = 0; j < 4; ++j) {
            int k = b_k + 8 * j;
            cpasync16(ab + ABYTES + k * (BPITCH*4) + b_n4 * 16,
                      Bg + (size_t)(k0 + k) * UU + b_n4 * 4);
        }
        asm volatile("cp.async.commit_group;" ::: "memory");
    }

    // per-lane fragment base offsets (bytes, within a buffer)
    const uint32_t aLane = (uint32_t)((Mw * 64 + g) * (APITCH*4) + tc * 4);
    const uint32_t bLane = (uint32_t)(tc * (BPITCH*4) + (Nw * 32 + g) * 4);

    int cur = 0, nxt = STAGES - 1;
    for (int c = 0; c < NCHUNK; ++c) {
        if (c + 1 < NCHUNK)
            asm volatile("cp.async.wait_group 1;" ::: "memory");
        else
            asm volatile("cp.async.wait_group 0;" ::: "memory");
        __syncthreads();

        // issue stage c+2 (overwrites buffer read in chunk c-1; safe after sync)
        if (c + STAGES - 1 < NCHUNK) {
            const uint32_t ab = sb + nxt * BUFBYTES;
            const int k0 = (c + STAGES - 1) * KC;
            #pragma unroll
            for (int j = 0; j < 4; ++j) {
                int row = a_row + 32 * j;
                cpasync16(ab + row * (APITCH*4) + a_k4 * 16,
                          Ag + (size_t)row * HH + k0 + a_k4 * 4);
            }
            #pragma unroll
            for (int j = 0; j < 4; ++j) {
                int k = b_k + 8 * j;
                cpasync16(ab + ABYTES + k * (BPITCH*4) + b_n4 * 16,
                          Bg + (size_t)(k0 + k) * UU + b_n4 * 4);
            }
            asm volatile("cp.async.commit_group;" ::: "memory");
        }

        // ---- compute chunk c from buffer cur ----
        const uint32_t bufo = cur * BUFBYTES;
        #pragma unroll
        for (int s = 0; s < 4; ++s) {
            uint32_t a[4][4];
            #pragma unroll
            for (int i = 0; i < 4; ++i) {
                const uint32_t* p = (const uint32_t*)(smem +
                    bufo + aLane + i * 16 * (APITCH*4) + s * 32);
                a[i][0] = p[0];
                a[i][1] = p[8 * APITCH];
                a[i][2] = p[4];
                a[i][3] = p[8 * APITCH + 4];
            }
            #pragma unroll
            for (int jn = 0; jn < 4; ++jn) {
                const uint32_t* q = (const uint32_t*)(smem +
                    bufo + ABYTES + bLane + s * 8 * (BPITCH*4) + jn * 32);
                uint32_t b0 = q[0];
                uint32_t b1 = q[4 * BPITCH];
                #pragma unroll
                for (int i = 0; i < 4; ++i)
                    mma_tf32(d[i][jn], a[i], b0, b1);
            }
        }
        cur = (cur == STAGES - 1) ? 0 : cur + 1;
        nxt = (nxt == STAGES - 1) ? 0 : nxt + 1;
    }

    // ---- fused epilogue: tanh(d + dec)*Va, reduce over u ----
    float rowacc[4][2] = {};
    #pragma unroll
    for (int i = 0; i < 4; ++i)
        #pragma unroll
        for (int jn = 0; jn < 4; ++jn)
            #pragma unroll
            for (int r = 0; r < 4; ++r) {
                int ul = Nw * 32 + jn * 8 + tc * 2 + (r & 1);
                float v = tanh_fast(d[i][jn][r] + s_dec[ul]) * s_va[ul];
                rowacc[i][r >> 1] += v;
            }
    #pragma unroll
    for (int i = 0; i < 4; ++i)
        #pragma unroll
        for (int h = 0; h < 2; ++h) {
            float v = rowacc[i][h];
            v += __shfl_xor_sync(0xffffffffu, v, 1);
            v += __shfl_xor_sync(0xffffffffu, v, 2);
            rowacc[i][h] = v;
        }
    if (tc == 0) {
        #pragma unroll
        for (int i = 0; i < 4; ++i)
            #pragma unroll
            for (int h = 0; h < 2; ++h) {
                int m = Mw * 64 + i * 16 + h * 8 + g;
                s_red[m * 4 + Nw] = rowacc[i][h];
            }
    }
    __syncthreads();
    if (tid < TM) {
        float s = s_red[tid * 4] + s_red[tid * 4 + 1]
                + s_red[tid * 4 + 2] + s_red[tid * 4 + 3];
        g_score_part[blockIdx.x][r0 + tid] = s;
    }
}

// ---------------------------------------------------------------------------
// Softmax over T (sums the 8 N-block partials). grid (B), 256 thr.
// ---------------------------------------------------------------------------
__global__ __launch_bounds__(256) void k_softmax() {
    int b = blockIdx.x, tid = threadIdx.x;
    __shared__ float sm[256];
    float* sc = g_score + b * TT;

    float m = -1e30f;
    for (int t = tid; t < TT; t += 256) {
        float v = 0.f;
        #pragma unroll
        for (int p = 0; p < NBLK; ++p) v += g_score_part[p][b * TT + t];
        sc[t] = v;
        m = fmaxf(m, v);
    }
    sm[tid] = m; __syncthreads();
    for (int s = 128; s > 0; s >>= 1) {
        if (tid < s) sm[tid] = fmaxf(sm[tid], sm[tid + s]);
        __syncthreads();
    }
    m = sm[0]; __syncthreads();

    float sum = 0.f;
    for (int t = tid; t < TT; t += 256) {
        float e = __expf(sc[t] - m);
        sc[t] = e; sum += e;
    }
    sm[tid] = sum; __syncthreads();
    for (int s = 128; s > 0; s >>= 1) {
        if (tid < s) sm[tid] += sm[tid + s];
        __syncthreads();
    }
    float inv = 1.f / sm[0];
    for (int t = tid; t < TT; t += 256) sc[t] *= inv;
}

// ---------------------------------------------------------------------------
// Context: grid (B, H/256, 16), block 256. Each block: 128 t's for 256 h's.
// ---------------------------------------------------------------------------
__global__ __launch_bounds__(256) void k_ctx_part(const float* __restrict__ enc) {
    int b = blockIdx.x, hc = blockIdx.y, tc = blockIdx.z;
    int h = hc * 256 + threadIdx.x;
    int t0 = tc * 128;
    __shared__ float s_al[128];
    if (threadIdx.x < 128) s_al[threadIdx.x] = g_score[b * TT + t0 + threadIdx.x];
    __syncthreads();
    float acc = 0.f;
    const float* e = enc + ((size_t)b * TT + t0) * HH + h;
    #pragma unroll 16
    for (int t = 0; t < 128; ++t) acc += s_al[t] * e[(size_t)t * HH];
    g_ctx_part[tc][b * HH + h] = acc;
}

__global__ __launch_bounds__(256) void k_ctx_final(float* __restrict__ out) {
    int idx = blockIdx.x * 256 + threadIdx.x;
    float s = 0.f;
    #pragma unroll
    for (int p = 0; p < 16; ++p) s += g_ctx_part[p][idx];
    out[idx] = s;
}

// ---------------------------------------------------------------------------
extern "C" void kernel_launch(void* const* d_in, const int* in_sizes, int n_in,
                              void* d_out, int out_size) {
    const float* enc = (const float*)d_in[0];
    const float* dec = (const float*)d_in[1];
    const float* Wa  = (const float*)d_in[2];
    const float* Ua  = (const float*)d_in[3];
    const float* Va  = (const float*)d_in[4];
    float* out = (float*)d_out;

    static int smem_set = 0;
    if (!smem_set) {
        cudaFuncSetAttribute(k_score_mma,
                             cudaFuncAttributeMaxDynamicSharedMemorySize,
                             SMEM_TOTAL);
        smem_set = 1;
    }

    k_dec_proj<<<dim3(BB, 4), 256>>>(dec, Wa);
    k_score_mma<<<dim3(NBLK, BT / TM), 256, SMEM_TOTAL>>>(enc, Ua, Va);
    k_softmax<<<BB, 256>>>();
    k_ctx_part<<<dim3(BB, HH / 256, 16), 256>>>(enc);
    k_ctx_final<<<(BB * HH) / 256, 256>>>(out);
}